// round 9
// baseline (speedup 1.0000x reference)
#include <cuda_runtime.h>

// Inputs (metadata order): z [8192*128] f32 (UNUSED), risk [B] f32, time [B] f32, event [B] i32.
// Output: single f32 scalar = mean hinge over pairs (time[i] < time[j] && event[i]==1).
//
// K1: warp-aggregated scatter of rows into 32 time-buckets (all rows -> g_J;
//     event rows -> g_I with risk+1 prestored).
// K2: 32x32 bucket-pair tiles, TPB=64 (2 i's/thread = 128 i-slots ~ bucket size):
//       bj <  bi : skip  |  bj > bi : FREE (no predicate, closed-form count)
//       bj == bi : MIXED (exact strict per-pair compare)
//     Double/u64 global accumulation; last block finalizes and resets all state
//     (idempotent under CUDA-graph replay).

#define NB    32
#define CAP   8192
#define TPB1  256
#define TPB   64
#define JT    64
#define NBLK2 (NB * NB)

__device__ float2             g_J[NB * CAP];   // (risk, time) per time-bucket
__device__ float2             g_I[NB * CAP];   // (risk+1, time), event rows only
__device__ int                g_cJ[NB];        // bucket counts (zeroed at load / by finalize)
__device__ int                g_cI[NB];
__device__ double             g_total;
__device__ unsigned long long g_cnt;
__device__ unsigned int       g_done;

// ---------------- K1: warp-aggregated bucket scatter ----------------
__global__ void k_scatter(const float* __restrict__ risk,
                          const float* __restrict__ time_,
                          const int*   __restrict__ event,
                          int n) {
    int r = blockIdx.x * blockDim.x + threadIdx.x;
    bool valid = (r < n);
    float t = 0.0f, rk = 0.0f;
    bool  e = false;
    int   b = 0;
    if (valid) {
        t  = time_[r];
        rk = risk[r];
        e  = (event[r] == 1);
        b  = (int)(t * (float)NB);
        b  = b < 0 ? 0 : (b > NB - 1 ? NB - 1 : b);
    }
    const int lane = threadIdx.x & 31;
    unsigned act = __ballot_sync(0xffffffffu, valid);

    if (valid) {
        // aggregate the all-rows scatter per (warp, bucket) group
        unsigned m      = __match_any_sync(act, b);
        int      leader = __ffs(m) - 1;
        int      rank   = __popc(m & ((1u << lane) - 1u));
        int      base   = 0;
        if (lane == leader) base = atomicAdd(&g_cJ[b], __popc(m));
        base = __shfl_sync(m, base, leader);
        g_J[b * CAP + base + rank] = make_float2(rk, t);
    }

    unsigned em = __ballot_sync(act, valid && e);
    if (valid && e) {
        unsigned m      = __match_any_sync(em, b);
        int      leader = __ffs(m) - 1;
        int      rank   = __popc(m & ((1u << lane) - 1u));
        int      base   = 0;
        if (lane == leader) base = atomicAdd(&g_cI[b], __popc(m));
        base = __shfl_sync(m, base, leader);
        g_I[b * CAP + base + rank] = make_float2(rk + 1.0f, t);
    }
}

// ---------------- K2: classified bucket-tile loop ----------------
__global__ __launch_bounds__(TPB) void k_tiles(float* __restrict__ out) {
    __shared__ float sjr[JT];          // risk_j
    __shared__ int   sjt[JT];          // time_j bits (times >= 0, or -inf pad)
    __shared__ float swsum[TPB / 32];
    __shared__ int   swcnt[TPB / 32];

    const int tid  = threadIdx.x;
    const int lane = tid & 31;
    const int w    = tid >> 5;
    const int bi   = blockIdx.x;
    const int bj   = blockIdx.y;

    float              s  = 0.0f;
    int                c  = 0;
    unsigned long long cf = 0ull;      // thread 0 only

    if (bj >= bi) {
        const int ni = g_cI[bi];
        const int nj = g_cJ[bj];
        if (ni > 0 && nj > 0) {
            const bool freeT = (bj > bi);
            if (freeT && tid == 0)
                cf = (unsigned long long)ni * (unsigned long long)nj;

            const float2* __restrict__ I = g_I + bi * CAP;
            const float2* __restrict__ J = g_J + bj * CAP;

            for (int i0 = 0; i0 < ni; i0 += 2 * TPB) {
                const int  ia  = i0 + 2 * tid;            // consecutive pair of i's
                const bool act = (ia < ni);
                float r0 = __int_as_float(0xff800000);    // -inf: hinge contributes 0
                float r1 = r0;
                int   t0b = 0x7f800000, t1b = 0x7f800000; // +inf bits: pred never true
                if (act) {
                    float2 u = I[ia];
                    r0 = u.x; t0b = __float_as_int(u.y);
                    if (ia + 1 < ni) { float2 v = I[ia + 1]; r1 = v.x; t1b = __float_as_int(v.y); }
                }

                float s0 = 0.f, s1 = 0.f;
                int   c0 = 0,   c1 = 0;

                for (int j0 = 0; j0 < nj; j0 += JT) {      // block-uniform bounds
                    __syncthreads();
                    {
                        int k = j0 + tid;
                        float rj  = __int_as_float(0x7f800000);  // +inf pad: free adds 0
                        int   tjb = 0xff800000;                  // -inf pad: pred false
                        if (k < nj) { float2 v = J[k]; rj = v.x; tjb = __float_as_int(v.y); }
                        sjr[tid] = rj;
                        sjt[tid] = tjb;
                    }
                    __syncthreads();

                    if (act) {
                        if (freeT) {
                            #pragma unroll 8
                            for (int k = 0; k < JT; k++) {
                                float rj = sjr[k];
                                s0 += fmaxf(r0 - rj, 0.0f);
                                s1 += fmaxf(r1 - rj, 0.0f);
                            }
                        } else {
                            #pragma unroll 8
                            for (int k = 0; k < JT; k++) {
                                float rj  = sjr[k];
                                int   tjb = sjt[k];
                                bool  p0  = tjb > t0b;
                                bool  p1  = tjb > t1b;
                                s0 += p0 ? fmaxf(r0 - rj, 0.0f) : 0.0f;
                                s1 += p1 ? fmaxf(r1 - rj, 0.0f) : 0.0f;
                                c0 += (int)p0;
                                c1 += (int)p1;
                            }
                        }
                    }
                }
                s += s0 + s1;
                c += c0 + c1;
            }
        }
    }

    // ---- reduce (2 warps) + global accumulate + finalize ----
    #pragma unroll
    for (int off = 16; off >= 1; off >>= 1) {
        s += __shfl_down_sync(0xffffffffu, s, off);
        c += __shfl_down_sync(0xffffffffu, c, off);
    }
    if (lane == 0) { swsum[w] = s; swcnt[w] = c; }
    __syncthreads();
    if (tid == 0) {
        float ss = swsum[0] + swsum[1];
        int   cc = swcnt[0] + swcnt[1];
        unsigned long long ctot = (unsigned long long)cc + cf;
        if (ss != 0.0f)   atomicAdd(&g_total, (double)ss);
        if (ctot != 0ull) atomicAdd(&g_cnt, ctot);
        __threadfence();
        unsigned int prev = atomicAdd(&g_done, 1u);
        if (prev == (unsigned int)NBLK2 - 1u) {
            __threadfence();
            double tt = *(volatile double*)&g_total;
            unsigned long long cn = *(volatile unsigned long long*)&g_cnt;
            out[0] = (cn != 0ull) ? (float)(tt / (double)cn) : 0.0f;
            // reset all state: launch sequence idempotent for next graph replay
            #pragma unroll
            for (int b = 0; b < NB; b++) { g_cJ[b] = 0; g_cI[b] = 0; }
            g_total = 0.0;
            g_cnt   = 0ull;
            g_done  = 0u;
        }
    }
}

extern "C" void kernel_launch(void* const* d_in, const int* in_sizes, int n_in,
                              void* d_out, int out_size) {
    const float* risk  = (const float*)d_in[1];
    const float* time_ = (const float*)d_in[2];
    const int*   event = (const int*)d_in[3];
    const int n = in_sizes[1];

    k_scatter<<<(n + TPB1 - 1) / TPB1, TPB1>>>(risk, time_, event, n);

    dim3 g2(NB, NB);
    k_tiles<<<g2, TPB>>>((float*)d_out);
}